// round 14
// baseline (speedup 1.0000x reference)
#include <cuda_runtime.h>

#define SEQ   128
#define BSZ   1024
#define DIN   37
#define QDIM  11
#define HID   256
#define MSLOT 20
#define ROWS  (BSZ*MSLOT)   // 20480
#define SB    (SEQ*BSZ)     // 131072

#define BM 64
#define KC 64

// fused-scan tiling
#define TROWS 80                 // rows per tile = 4 batches exactly
#define RPT   10                 // rows per thread (8 warps x 10 = 80)
#define KCP   16                 // panel K depth
#define NPAN  32                 // panels per step (16 U + 16 J1)
#define NTILES (ROWS/TROWS)      // 256
#define SCAN_GRID 148
#define PAN_BYTES (KCP*256*4)    // 16384
#define PAN_FLOATS (KCP*256)

typedef unsigned long long ull;

// ---------------- scratch (no cudaMalloc allowed) ----------------
__device__ float g_mi[(size_t)SB*HID];
__device__ float g_tmp[(size_t)SB*HID];
__device__ float g_sentJ[(size_t)SB*HID];
__device__ float g_mem[(size_t)ROWS*HID];
__device__ float g_q[(size_t)BSZ*HID];
__device__ float g_a3[(size_t)MSLOT*HID];
__device__ float g_keyJ[(size_t)MSLOT*HID];
__device__ float g_cat[(size_t)BSZ*2*HID];
__device__ float g_gateE[(size_t)SB*MSLOT];          // sent . embed per (s,b,m)
__device__ float g_wT[4*(size_t)HID*HID];            // Ut, J1t, Vt, J2t (k-major)
__device__ float g_Ct[40*HID];                       // C_w padded k-major [40][256]

// ---------------- f32x2 / cp.async helpers ----------------
__device__ __forceinline__ ull splat2(float a) {
    ull r; asm("mov.b64 %0, {%1, %1};" : "=l"(r) : "f"(a)); return r;
}
__device__ __forceinline__ void ffma2(ull& acc, ull a, ull b) {
    asm("fma.rn.f32x2 %0, %1, %2, %0;" : "+l"(acc) : "l"(a), "l"(b));
}
__device__ __forceinline__ float2 unpack2(ull v) {
    float2 f; asm("mov.b64 {%0, %1}, %2;" : "=f"(f.x), "=f"(f.y) : "l"(v)); return f;
}
__device__ __forceinline__ unsigned smem_u32(const void* p) {
    unsigned r;
    asm("{ .reg .u64 t; cvta.to.shared.u64 t, %1; cvt.u32.u64 %0, t; }" : "=r"(r) : "l"(p));
    return r;
}
__device__ __forceinline__ void cp_async16(unsigned saddr, const void* gptr) {
    asm volatile("cp.async.cg.shared.global [%0], [%1], 16;" :: "r"(saddr), "l"(gptr));
}
__device__ __forceinline__ void cp_commit() {
    asm volatile("cp.async.commit_group;");
}
template <int N>
__device__ __forceinline__ void cp_wait() {
    asm volatile("cp.async.wait_group %0;" :: "n"(N));
}

// issue one KCP x 256 panel (float4 copies, conflict-free)
__device__ __forceinline__ void issue_panel(const float* __restrict__ src,
                                            float* __restrict__ dst, int tid)
{
    unsigned d = smem_u32(dst) + (unsigned)tid * 16u;
    const float4* g = (const float4*)src + tid;
#pragma unroll
    for (int q = 0; q < (KCP*256)/(256*4); q++)   // 4 chunks
        cp_async16(d + q*256*16, g + q*256);
    cp_commit();
}

// core f32x2 micro-GEMM over one KCPx256 panel.
// Column mapping: lane ct owns cols {4ct..4ct+3} (acc[.][0..1]) and
// {128+4ct..128+4ct+3} (acc[.][2..3]).
// A loads vectorized: one broadcast LDS.128 per row per 4 k.
template <int R>
__device__ __forceinline__ void compute_panel16(const float* __restrict__ pan,
    const float* __restrict__ A, int k0, ull acc[R][4], int rbase, int ct)
{
#pragma unroll
    for (int kq = 0; kq < KCP/4; kq++) {
        float av[R][4];
#pragma unroll
        for (int i = 0; i < R; i++)
            *(float4*)av[i] = *(const float4*)(A + (rbase + i)*256 + k0 + 4*kq);
#pragma unroll
        for (int kk = 0; kk < 4; kk++) {
            const float* bp = pan + (4*kq + kk)*256 + 4*ct;
            ulonglong2 b01 = *(const ulonglong2*)(bp);
            ulonglong2 b23 = *(const ulonglong2*)(bp + 128);
#pragma unroll
            for (int i = 0; i < R; i++) {
                ull a2 = splat2(av[i][kk]);
                ffma2(acc[i][0], a2, b01.x);
                ffma2(acc[i][1], a2, b01.y);
                ffma2(acc[i][2], a2, b23.x);
                ffma2(acc[i][3], a2, b23.y);
            }
        }
    }
}

// epilogue column for accumulator slot j (new mapping)
__device__ __forceinline__ int slot_col(int ct, int j) {
    return ((j >> 1) * 128) + 4*ct + 2*(j & 1);
}

// ---------------- generic scalar GEMM (tiny cases only) ----------------
__global__ void __launch_bounds__(256) gemm256(
    const float* __restrict__ A, int lda, int rows, int K,
    const float* __restrict__ B, int ldb,
    const float* __restrict__ bias,
    float* __restrict__ C, int act)
{
    extern __shared__ float sm[];
    float* sA    = sm;                 // BM*KC
    float* sB    = sm + BM*KC;         // KC*257
    float* sBias = sB + KC*257;        // 256

    int tid = threadIdx.x;
    int rt = tid >> 5, ct = tid & 31;
    long r0 = (long)blockIdx.x * BM;

    sBias[tid] = bias ? bias[tid] : 0.f;

    float acc[8][8];
#pragma unroll
    for (int i = 0; i < 8; i++)
#pragma unroll
        for (int j = 0; j < 8; j++) acc[i][j] = 0.f;

    for (int k0 = 0; k0 < K; k0 += KC) {
#pragma unroll 4
        for (int t = tid; t < BM*KC; t += 256) {
            int row = t >> 6, kk = t & 63;
            int k = k0 + kk;
            long r = r0 + row;
            sA[t] = (k < K && r < rows) ? A[r*(long)lda + k] : 0.f;
        }
#pragma unroll 8
        for (int t = tid; t < 256*KC; t += 256) {
            int n = t >> 6, kk = t & 63;
            int k = k0 + kk;
            sB[kk*257 + n] = (k < K) ? B[(long)n*ldb + k] : 0.f;
        }
        __syncthreads();
#pragma unroll 8
        for (int kk = 0; kk < KC; kk++) {
            float a[8], bv[8];
#pragma unroll
            for (int i = 0; i < 8; i++) a[i] = sA[(rt*8 + i)*KC + kk];
#pragma unroll
            for (int j = 0; j < 8; j++) bv[j] = sB[kk*257 + ct + j*32];
#pragma unroll
            for (int i = 0; i < 8; i++)
#pragma unroll
                for (int j = 0; j < 8; j++) acc[i][j] = fmaf(a[i], bv[j], acc[i][j]);
        }
        __syncthreads();
    }
#pragma unroll
    for (int i = 0; i < 8; i++) {
        long row = r0 + rt*8 + i;
        if (row < rows) {
#pragma unroll
            for (int j = 0; j < 8; j++) {
                int col = ct + j*32;
                float v = acc[i][j] + sBias[col];
                if (act == 1) v = fmaxf(v, 0.f);
                C[row*256 + col] = v;
            }
        }
    }
}

// ---------------- f32x2 GEMM, K=256, N=256, Bt k-major, cp.async panels ----------------
__global__ void __launch_bounds__(256,2) gemm_ffma2(
    const float* __restrict__ A,
    const float* __restrict__ Bt,
    const float* __restrict__ bias,
    float* __restrict__ C, int act)
{
    extern __shared__ float sm[];
    float* sA    = sm;                // 64*256
    float* sPan  = sA + 64*256;       // 3*KCP*256
    float* sBias = sPan + 3*PAN_FLOATS;

    int tid = threadIdx.x;
    int warp = tid >> 5, ct = tid & 31;
    int rbase = warp * 8;
    long r0 = (long)blockIdx.x * 64;

    sBias[tid] = bias ? bias[tid] : 0.f;
    {
        const float4* g4 = (const float4*)(A + r0*256);
        float4* s4 = (float4*)sA;
#pragma unroll 4
        for (int i = tid; i < 64*64; i += 256) s4[i] = g4[i];
    }
    issue_panel(Bt + 0*PAN_FLOATS, sPan + 0*PAN_FLOATS, tid);
    issue_panel(Bt + 1*PAN_FLOATS, sPan + 1*PAN_FLOATS, tid);

    ull acc[8][4];
#pragma unroll
    for (int i = 0; i < 8; i++)
#pragma unroll
        for (int j = 0; j < 4; j++) acc[i][j] = 0ull;

    for (int p = 0; p < 16; p++) {
        if (p < 15) cp_wait<1>(); else cp_wait<0>();
        __syncthreads();
        if (p + 2 < 16)
            issue_panel(Bt + (size_t)(p+2)*PAN_FLOATS, sPan + ((p+2)%3)*PAN_FLOATS, tid);
        compute_panel16<8>(sPan + (p%3)*PAN_FLOATS, sA, p*KCP, acc, rbase, ct);
    }

#pragma unroll
    for (int i = 0; i < 8; i++) {
        long row = r0 + rbase + i;
#pragma unroll
        for (int j = 0; j < 4; j++) {
            int col = slot_col(ct, j);
            float2 v = unpack2(acc[i][j]);
            v.x += sBias[col];
            v.y += sBias[col+1];
            if (act) { v.x = fmaxf(v.x, 0.f); v.y = fmaxf(v.y, 0.f); }
            *(float2*)(C + row*256 + col) = v;
        }
    }
}

// ---------------- dedicated K=37 GEMM: mi = relu(memory_inputs @ C^T + Cb) ----------------
// (old 2ct/stride-64 column mapping; self-consistent within this kernel)
__global__ void __launch_bounds__(256) mi_kernel(
    const float* __restrict__ A,       // [SB][37]
    const float* __restrict__ Ct,      // [40][256] k-major padded
    const float* __restrict__ Cb,
    float* __restrict__ Cout)
{
    extern __shared__ float sm[];
    float* sA    = sm;
    float* sW    = sm + 64*DIN;
    float* sBias = sW + 40*256;

    int tid = threadIdx.x;
    int warp = tid >> 5, ct = tid & 31;
    int rbase = warp * 8;
    long r0 = (long)blockIdx.x * 64;

    {
        unsigned d = smem_u32(sA);
        // A tile: 64 rows x 37 floats = 2368 floats = 592 float4
        const float4* g = (const float4*)(A + r0*DIN);
        for (int i = tid; i < 592; i += 256)
            cp_async16(d + i*16u, g + i);
        unsigned dw = smem_u32(sW);
        const float4* gw = (const float4*)Ct;
        for (int i = tid; i < 40*64; i += 256)
            cp_async16(dw + i*16u, gw + i);
        cp_commit();
    }
    sBias[tid] = Cb[tid];
    cp_wait<0>();
    __syncthreads();

    ull acc[8][4];
#pragma unroll
    for (int i = 0; i < 8; i++)
#pragma unroll
        for (int j = 0; j < 4; j++) acc[i][j] = 0ull;

#pragma unroll 1
    for (int kk = 0; kk < DIN; kk++) {
        const float* bp = sW + kk*256 + 2*ct;
        ull b0 = *(const ull*)(bp);
        ull b1 = *(const ull*)(bp + 64);
        ull b2 = *(const ull*)(bp + 128);
        ull b3 = *(const ull*)(bp + 192);
#pragma unroll
        for (int i = 0; i < 8; i++) {
            ull a2 = splat2(sA[(rbase + i)*DIN + kk]);
            ffma2(acc[i][0], a2, b0);
            ffma2(acc[i][1], a2, b1);
            ffma2(acc[i][2], a2, b2);
            ffma2(acc[i][3], a2, b3);
        }
    }

#pragma unroll
    for (int i = 0; i < 8; i++) {
        long row = r0 + rbase + i;
#pragma unroll
        for (int j = 0; j < 4; j++) {
            int col = 2*(ct + 32*j);
            float2 v = unpack2(acc[i][j]);
            v.x = fmaxf(v.x + sBias[col],   0.f);
            v.y = fmaxf(v.y + sBias[col+1], 0.f);
            *(float2*)(Cout + row*256 + col) = v;
        }
    }
}

// ---------------- 256x256 transpose: out[k][n] = in[n][k] ----------------
__global__ void transpose256(const float* __restrict__ in, int ldin, float* __restrict__ out)
{
    __shared__ float tl[32][33];
    int bx = blockIdx.x*32, by = blockIdx.y*32;
    int tx = threadIdx.x, ty = threadIdx.y;
#pragma unroll
    for (int r = 0; r < 4; r++)
        tl[ty + 8*r][tx] = in[(long)(by + ty + 8*r)*ldin + bx + tx];
    __syncthreads();
#pragma unroll
    for (int r = 0; r < 4; r++)
        out[(long)(bx + ty + 8*r)*256 + by + tx] = tl[tx][ty + 8*r];
}

// C_w [256][37] -> padded k-major [40][256]
__global__ void padtransC(const float* __restrict__ C_w, float* __restrict__ Ct)
{
    int k = blockIdx.x, n = threadIdx.x;
    Ct[k*256 + n] = (k < DIN) ? C_w[n*DIN + k] : 0.f;
}

// ---------------- gateE = mi @ embed^T  (SB x 20) ----------------
__global__ void __launch_bounds__(256) gatee_kernel(
    const float* __restrict__ mi, const float* __restrict__ embed, float* __restrict__ out)
{
    extern __shared__ float sm[];
    float* sMi = sm;            // 64*256
    float* sE  = sm + 64*256;   // 20*256
    int tid = threadIdx.x, ct = tid & 31;
    long r0 = (long)blockIdx.x * 64;
    {
        const float4* g4 = (const float4*)(mi + r0*256);
        float4* s4 = (float4*)sMi;
#pragma unroll 4
        for (int i = tid; i < 64*64; i += 256) s4[i] = g4[i];
        const float4* e4 = (const float4*)embed;
        float4* se4 = (float4*)sE;
        for (int i = tid; i < 20*64; i += 256) se4[i] = e4[i];
    }
    __syncthreads();
#pragma unroll
    for (int q = 0; q < 5; q++) {
        int o = q*256 + tid;
        int row = o / 20, m = o % 20;
        float acc = 0.f;
#pragma unroll 8
        for (int k = 0; k < 256; k++) {
            int kr = (k + ct*8) & 255;
            acc += sMi[row*256 + kr] * sE[m*256 + kr];
        }
        out[r0*20 + o] = acc;
    }
}

// ---------------- fused persistent scan (cp.async panels, f32x2 core) ----------------
__global__ void __launch_bounds__(256,1) scan_kernel(
    const float* __restrict__ Ut, const float* __restrict__ J1t,
    const float* __restrict__ U_b, const float* __restrict__ J_b,
    const float* __restrict__ prelu_a,
    const float* __restrict__ mi, const float* __restrict__ sentJ,
    const float* __restrict__ gateE, const float* __restrict__ keyJ,
    float* __restrict__ mem)
{
    extern __shared__ float sm[];
    float* sMem  = sm;                       // 80*256 = 20480
    float* sA1   = sMem + TROWS*256;         // 20480
    float* sPan  = sA1  + TROWS*256;         // 3*16*256 = 12288
    float* sSent = sPan + 3*PAN_FLOATS;      // 4*256
    float* sSJ   = sSent + 4*256;            // 4*256
    float* sUb   = sSJ   + 4*256;            // 256
    float* sJb   = sUb   + 256;              // 256

    int tid = threadIdx.x;
    int warp = tid >> 5, ct = tid & 31;
    int rbase = warp * RPT;
    float alpha = prelu_a[0];
    sUb[tid] = U_b[tid];
    sJb[tid] = J_b[tid];

    int t0 = (blockIdx.x     * NTILES) / SCAN_GRID;
    int t1 = ((blockIdx.x+1) * NTILES) / SCAN_GRID;

    for (int t = t0; t < t1; t++) {
        int r0 = t * TROWS;
        int b0 = t * 4;
        __syncthreads();                      // prev tile store done
        {
            const float4* g4 = (const float4*)(mem + (size_t)r0*256);
            float4* s4 = (float4*)sMem;
#pragma unroll 4
            for (int i = tid; i < TROWS*64; i += 256) s4[i] = g4[i];
        }

        for (int s = 0; s < SEQ; s++) {
            __syncthreads();                  // epilogue done; sSent/sSJ free
            {
                const float4* g1 = (const float4*)(mi    + ((size_t)s*BSZ + b0)*256);
                const float4* g2 = (const float4*)(sentJ + ((size_t)s*BSZ + b0)*256);
                ((float4*)sSent)[tid] = g1[tid];   // 4 batches
                ((float4*)sSJ)[tid]   = g2[tid];
            }
            issue_panel(Ut + 0*PAN_FLOATS, sPan + 0*PAN_FLOATS, tid);
            issue_panel(Ut + 1*PAN_FLOATS, sPan + 1*PAN_FLOATS, tid);
            __syncthreads();

            // ---- gate ----
            float gv[RPT];
#pragma unroll
            for (int i = 0; i < RPT; i++) {
                int lr = rbase + i;
                const float* se = sSent + (lr/20)*256;
                float pr = 0.f;
#pragma unroll
                for (int q = 0; q < 8; q++) {
                    int k = ct + q*32;
                    pr += se[k] * sMem[lr*256 + k];
                }
#pragma unroll
                for (int o = 16; o > 0; o >>= 1) pr += __shfl_xor_sync(0xffffffffu, pr, o);
                pr += gateE[(size_t)s*ROWS + r0 + lr];
                gv[i] = 1.f / (1.f + expf(-pr));
            }

            ull acc[RPT][4];
#pragma unroll
            for (int i = 0; i < RPT; i++)
#pragma unroll
                for (int j = 0; j < 4; j++) acc[i][j] = 0ull;

            for (int p = 0; p < NPAN; p++) {
                if (p < NPAN-1) cp_wait<1>(); else cp_wait<0>();
                __syncthreads();
                int pn = p + 2;
                if (pn < NPAN) {
                    const float* src = (pn < 16) ? (Ut + (size_t)pn*PAN_FLOATS)
                                                 : (J1t + (size_t)(pn-16)*PAN_FLOATS);
                    issue_panel(src, sPan + (pn%3)*PAN_FLOATS, tid);
                }
                const float* A = (p < 16) ? sMem : sA1;
                compute_panel16<RPT>(sPan + (p%3)*PAN_FLOATS, A, (p & 15)*KCP, acc, rbase, ct);

                if (p == 15) {
                    // A1 = relu(acc + U_b) (float4 stores), reset acc for GEMM2
                    float4 ub0 = *(const float4*)(sUb + 4*ct);
                    float4 ub1 = *(const float4*)(sUb + 128 + 4*ct);
#pragma unroll
                    for (int i = 0; i < RPT; i++) {
                        float2 c0 = unpack2(acc[i][0]);
                        float2 c1 = unpack2(acc[i][1]);
                        float2 c2 = unpack2(acc[i][2]);
                        float2 c3 = unpack2(acc[i][3]);
                        float4 v0, v1;
                        v0.x = fmaxf(c0.x + ub0.x, 0.f);
                        v0.y = fmaxf(c0.y + ub0.y, 0.f);
                        v0.z = fmaxf(c1.x + ub0.z, 0.f);
                        v0.w = fmaxf(c1.y + ub0.w, 0.f);
                        v1.x = fmaxf(c2.x + ub1.x, 0.f);
                        v1.y = fmaxf(c2.y + ub1.y, 0.f);
                        v1.z = fmaxf(c3.x + ub1.z, 0.f);
                        v1.w = fmaxf(c3.y + ub1.w, 0.f);
                        *(float4*)(sA1 + (rbase+i)*256 + 4*ct)       = v0;
                        *(float4*)(sA1 + (rbase+i)*256 + 128 + 4*ct) = v1;
                        acc[i][0] = acc[i][1] = acc[i][2] = acc[i][3] = 0ull;
                    }
                }
            }

            // ---- epilogue: prelu, gated update, normalize; float4 traffic ----
            {
                float4 jb0 = *(const float4*)(sJb + 4*ct);
                float4 jb1 = *(const float4*)(sJb + 128 + 4*ct);
#pragma unroll
                for (int i = 0; i < RPT; i++) {
                    int lr = rbase + i;
                    int m  = lr % MSLOT;
                    float g = gv[i];
                    const float* sj = sSJ + (lr/20)*256;
                    const float* kj = keyJ + m*256;
                    float4 sj0 = *(const float4*)(sj + 4*ct);
                    float4 sj1 = *(const float4*)(sj + 128 + 4*ct);
                    float4 kj0 = *(const float4*)(kj + 4*ct);
                    float4 kj1 = *(const float4*)(kj + 128 + 4*ct);
                    float4 m0 = *(const float4*)(sMem + lr*256 + 4*ct);
                    float4 m1 = *(const float4*)(sMem + lr*256 + 128 + 4*ct);
                    float2 c0 = unpack2(acc[i][0]);
                    float2 c1 = unpack2(acc[i][1]);
                    float2 c2 = unpack2(acc[i][2]);
                    float2 c3 = unpack2(acc[i][3]);
                    float cv[8];
                    cv[0] = c0.x + jb0.x + sj0.x + kj0.x;
                    cv[1] = c0.y + jb0.y + sj0.y + kj0.y;
                    cv[2] = c1.x + jb0.z + sj0.z + kj0.z;
                    cv[3] = c1.y + jb0.w + sj0.w + kj0.w;
                    cv[4] = c2.x + jb1.x + sj1.x + kj1.x;
                    cv[5] = c2.y + jb1.y + sj1.y + kj1.y;
                    cv[6] = c3.x + jb1.z + sj1.z + kj1.z;
                    cv[7] = c3.y + jb1.w + sj1.w + kj1.w;
                    float u[8];
                    float mm[8] = {m0.x, m0.y, m0.z, m0.w, m1.x, m1.y, m1.z, m1.w};
                    float ss = 0.f;
#pragma unroll
                    for (int e = 0; e < 8; e++) {
                        float cc = cv[e] > 0.f ? cv[e] : alpha * cv[e];
                        u[e] = mm[e] + g * cc;
                        ss += u[e] * u[e];
                    }
#pragma unroll
                    for (int o = 16; o > 0; o >>= 1) ss += __shfl_xor_sync(0xffffffffu, ss, o);
                    float inv = 1.f / (sqrtf(ss) + 1e-12f);
                    float4 w0, w1;
                    w0.x = u[0]*inv; w0.y = u[1]*inv; w0.z = u[2]*inv; w0.w = u[3]*inv;
                    w1.x = u[4]*inv; w1.y = u[5]*inv; w1.z = u[6]*inv; w1.w = u[7]*inv;
                    *(float4*)(sMem + lr*256 + 4*ct)       = w0;
                    *(float4*)(sMem + lr*256 + 128 + 4*ct) = w1;
                }
            }
        }

        __syncthreads();
        {
            const float4* s4 = (const float4*)sMem;
            float4* g4 = (float4*)(mem + (size_t)r0*256);
#pragma unroll 4
            for (int i = tid; i < TROWS*64; i += 256) g4[i] = s4[i];
        }
    }
}

// ---------------- memories init: mem[b*20+m][d] = embed[m][d] ----------------
__global__ void init_mem_kernel(const float* __restrict__ embed, float* __restrict__ mem)
{
    long idx = (long)blockIdx.x * 256 + threadIdx.x;
    int d = idx & 255;
    long rm = idx >> 8;
    int m = (int)(rm % MSLOT);
    mem[idx] = embed[m*256 + d];
}

// ---------------- attention + concat ----------------
__global__ void __launch_bounds__(256) attn_kernel(
    const float* __restrict__ mem, const float* __restrict__ q, float* __restrict__ cat)
{
    __shared__ float sQ[256];
    __shared__ float sM[MSLOT*256];
    __shared__ float sE[MSLOT];
    int b = blockIdx.x, tid = threadIdx.x;
    sQ[tid] = q[(long)b*256 + tid];
    for (int t = tid; t < MSLOT*256; t += 256) sM[t] = mem[(long)b*MSLOT*256 + t];
    __syncthreads();
    int w = tid >> 5, l = tid & 31;
    for (int m = w; m < MSLOT; m += 8) {
        float p = 0.f;
        for (int k = l; k < 256; k += 32) p += sM[m*256 + k] * sQ[k];
#pragma unroll
        for (int o = 16; o > 0; o >>= 1) p += __shfl_xor_sync(0xffffffffu, p, o);
        if (l == 0) sE[m] = p;
    }
    __syncthreads();
    float mx = -1e30f;
    for (int m = 0; m < MSLOT; m++) mx = fmaxf(mx, sE[m]);
    float sum = 0.f;
    for (int m = 0; m < MSLOT; m++) sum += expf(sE[m] - mx);
    float att = 0.f;
    for (int m = 0; m < MSLOT; m++) att += sM[m*256 + tid] * expf(sE[m] - mx);
    att /= sum;
    cat[(long)b*512 + tid]       = sQ[tid];
    cat[(long)b*512 + 256 + tid] = att;
}

// ---------------- host launcher ----------------
extern "C" void kernel_launch(void* const* d_in, const int* in_sizes, int n_in,
                              void* d_out, int out_size)
{
    const float* memory_inputs = (const float*)d_in[0];
    const float* question      = (const float*)d_in[1];
    const float* C_w = (const float*)d_in[2];
    const float* C_b = (const float*)d_in[3];
    const float* Q_w = (const float*)d_in[4];
    const float* Q_b = (const float*)d_in[5];
    const float* H_w = (const float*)d_in[6];
    const float* H_b = (const float*)d_in[7];
    const float* U_w = (const float*)d_in[8];
    const float* U_b = (const float*)d_in[9];
    const float* V_w = (const float*)d_in[10];
    const float* V_b = (const float*)d_in[11];
    const float* W_w = (const float*)d_in[12];
    const float* W_b = (const float*)d_in[13];
    const float* J_w = (const float*)d_in[14];
    const float* J_b = (const float*)d_in[15];
    const float* prelu_a = (const float*)d_in[16];
    const float* embed   = (const float*)d_in[17];
    float* out = (float*)d_out;

    size_t gemm_smem  = (size_t)(BM*KC + KC*257 + 256) * sizeof(float);
    size_t gx2_smem   = (size_t)(64*256 + 3*PAN_FLOATS + 256) * sizeof(float);
    size_t mi_smem    = (size_t)(64*DIN + 40*256 + 256) * sizeof(float);
    size_t scan_smem  = (size_t)(TROWS*256*2 + 3*PAN_FLOATS + 4*256*2 + 512) * sizeof(float);
    size_t gatee_smem = (size_t)(64*256 + 20*256) * sizeof(float);
    cudaFuncSetAttribute(gemm256,      cudaFuncAttributeMaxDynamicSharedMemorySize, (int)gemm_smem);
    cudaFuncSetAttribute(gemm_ffma2,   cudaFuncAttributeMaxDynamicSharedMemorySize, (int)gx2_smem);
    cudaFuncSetAttribute(mi_kernel,    cudaFuncAttributeMaxDynamicSharedMemorySize, (int)mi_smem);
    cudaFuncSetAttribute(scan_kernel,  cudaFuncAttributeMaxDynamicSharedMemorySize, (int)scan_smem);
    cudaFuncSetAttribute(gatee_kernel, cudaFuncAttributeMaxDynamicSharedMemorySize, (int)gatee_smem);

    float *mi, *tmp, *sentJ, *memb, *q, *a3, *keyJ, *cat, *gateE, *wT, *Ct;
    cudaGetSymbolAddress((void**)&mi,    g_mi);
    cudaGetSymbolAddress((void**)&tmp,   g_tmp);
    cudaGetSymbolAddress((void**)&sentJ, g_sentJ);
    cudaGetSymbolAddress((void**)&memb,  g_mem);
    cudaGetSymbolAddress((void**)&q,     g_q);
    cudaGetSymbolAddress((void**)&a3,    g_a3);
    cudaGetSymbolAddress((void**)&keyJ,  g_keyJ);
    cudaGetSymbolAddress((void**)&cat,   g_cat);
    cudaGetSymbolAddress((void**)&gateE, g_gateE);
    cudaGetSymbolAddress((void**)&wT,    g_wT);
    cudaGetSymbolAddress((void**)&Ct,    g_Ct);
    float* Ut  = wT;
    float* J1t = wT + (size_t)HID*HID;
    float* Vt  = wT + 2*(size_t)HID*HID;
    float* J2t = wT + 3*(size_t)HID*HID;

    // weight transposes (one-time, tiny)
    dim3 tb(32, 8), tg(8, 8);
    transpose256<<<tg, tb>>>(U_w, 256, Ut);
    transpose256<<<tg, tb>>>(J_w, 768, J1t);
    transpose256<<<tg, tb>>>(V_w, 256, Vt);
    transpose256<<<tg, tb>>>(J_w + 256, 768, J2t);
    padtransC<<<40, 256>>>(C_w, Ct);

    // init recurrent state
    init_mem_kernel<<<ROWS, 256>>>(embed, memb);

    // precompute
    mi_kernel<<<SB/64, 256, mi_smem>>>(memory_inputs, Ct, C_b, mi);
    gemm256<<<BSZ/BM, 256, gemm_smem>>>(question, QDIM, BSZ, QDIM, Q_w, QDIM, Q_b, q, 1);
    gatee_kernel<<<SB/64, 256, gatee_smem>>>(mi, embed, gateE);
    gemm_ffma2<<<SB/64, 256, gx2_smem>>>(mi, Vt, V_b, tmp, 1);
    gemm_ffma2<<<SB/64, 256, gx2_smem>>>(tmp, J2t, (const float*)0, sentJ, 0);
    gemm256<<<1, 256, gemm_smem>>>(embed, HID, MSLOT, HID, W_w, HID, W_b, a3, 1);
    gemm256<<<1, 256, gemm_smem>>>(a3, HID, MSLOT, HID, J_w + 512, 768, (const float*)0, keyJ, 0);

    // fused persistent scan
    scan_kernel<<<SCAN_GRID, 256, scan_smem>>>(Ut, J1t, U_b, J_b, prelu_a,
                                               mi, sentJ, gateE, keyJ, memb);

    // attention + concat, then final projection
    attn_kernel<<<BSZ, 256>>>(memb, q, cat);
    gemm256<<<BSZ/BM, 256, gemm_smem>>>(cat, 2*HID, BSZ, 2*HID, H_w, 2*HID, H_b, out, 1);
}

// round 16
// speedup vs baseline: 1.3944x; 1.3944x over previous
#include <cuda_runtime.h>
#include <cuda_bf16.h>
#include <cstdint>

#define SEQ 128
#define BSZ 1024
#define DIN 37
#define QDIM 11
#define HID 256
#define MSLOT 20
#define ROWS (BSZ*HID/HID*MSLOT)   // 20480
#define SB (SEQ*BSZ)
#define BM 64
#define KC 64

// scan smem byte offsets (dynamic base)
#define SHI 0u
#define SLO 67584u
#define OB  135168u
#define OSE 176128u
#define OSJ 184320u
#define OUB 192512u
#define OKJ 193536u
#define STOT 214016u

__device__ float g_mi[(size_t)SB*HID];
__device__ float g_tmp[(size_t)SB*HID];
__device__ float g_sentJ[(size_t)SB*HID];
__device__ float g_mem[(size_t)BSZ*MSLOT*HID];
__device__ float g_q[(size_t)BSZ*HID];
__device__ float g_a3[(size_t)MSLOT*HID];
__device__ float g_keyJ[(size_t)MSLOT*HID];
__device__ float g_cat[(size_t)BSZ*2*HID];
__device__ float g_gateE[(size_t)SB*MSLOT];
__device__ __nv_bfloat16 g_wimg[32*8192];

__device__ __forceinline__ unsigned smem_u32(const void* p){
    unsigned r; asm("{ .reg .u64 t; cvta.to.shared.u64 t, %1; cvt.u32.u64 %0, t; }":"=r"(r):"l"(p)); return r;
}
__device__ __forceinline__ void cp_async16(unsigned s,const void* g){
    asm volatile("cp.async.cg.shared.global [%0], [%1], 16;"::"r"(s),"l"(g));
}
__device__ __forceinline__ void cp_commit(){ asm volatile("cp.async.commit_group;"); }
template<int N> __device__ __forceinline__ void cp_wait(){ asm volatile("cp.async.wait_group %0;"::"n"(N)); }

__device__ __forceinline__ void ldsm4(uint32_t* r, unsigned a){
    asm volatile("ldmatrix.sync.aligned.m8n8.x4.shared.b16 {%0,%1,%2,%3}, [%4];"
        :"=r"(r[0]),"=r"(r[1]),"=r"(r[2]),"=r"(r[3]):"r"(a));
}
__device__ __forceinline__ void mma_(float* c, const uint32_t* a, uint32_t b0, uint32_t b1){
    asm volatile("mma.sync.aligned.m16n8k16.row.col.f32.bf16.bf16.f32 "
        "{%0,%1,%2,%3},{%4,%5,%6,%7},{%8,%9},{%0,%1,%2,%3};"
        :"+f"(c[0]),"+f"(c[1]),"+f"(c[2]),"+f"(c[3])
        :"r"(a[0]),"r"(a[1]),"r"(a[2]),"r"(a[3]),"r"(b0),"r"(b1));
}
__device__ __forceinline__ float2 bf2u(uint32_t w){
    __nv_bfloat162 t=*(__nv_bfloat162*)&w; return make_float2(__bfloat162float(t.x),__bfloat162float(t.y));
}
__device__ __forceinline__ uint32_t packsplit(float a,float b,uint32_t& lo){
    __nv_bfloat16 ha=__float2bfloat16(a), hb=__float2bfloat16(b);
    __nv_bfloat162 L; L.x=__float2bfloat16(a-__bfloat162float(ha)); L.y=__float2bfloat16(b-__bfloat162float(hb));
    lo=*(uint32_t*)&L; __nv_bfloat162 H; H.x=ha; H.y=hb; return *(uint32_t*)&H;
}

// weight chunk images: c = g*16 + h*8 + kc ; content [p][n128][k32] bf16
__global__ void wgt_build(const float* __restrict__ U_w, const float* __restrict__ J_w,
                          __nv_bfloat16* __restrict__ out)
{
    int c = blockIdx.x;
    int g = (c>>4)&1, h = (c>>3)&1, kc = c&7;
    const float* W = g ? J_w : U_w;
    int ld = g ? 768 : 256;
    __nv_bfloat16* dst = out + (size_t)c*8192;
    for (int e = threadIdx.x; e < 8192; e += 256) {
        int p = e>>12, n = (e>>5)&127, k = e&31;
        float w = W[(size_t)(h*128+n)*ld + kc*32 + k];
        __nv_bfloat16 hi = __float2bfloat16(w);
        dst[e] = p ? __float2bfloat16(w - __bfloat162float(hi)) : hi;
    }
}

__device__ __forceinline__ void cp_chunk(const __nv_bfloat16* wimg, unsigned dst, int img, int tid){
    const char* src = (const char*)wimg + (size_t)img*16384;
#pragma unroll
    for (int it=0; it<4; it++){
        int ci = tid + it*256;
        int p = ci>>9, n = (ci>>2)&127, u = ci&3;
        cp_async16(dst + (unsigned)(p*10240 + n*80 + u*16), src + p*8192 + n*64 + u*16);
    }
    cp_commit();
}

__global__ void __launch_bounds__(256,1) scan_mma(
    const float* __restrict__ Ub_, const float* __restrict__ Jb_,
    const float* __restrict__ pa,
    const float* __restrict__ mi, const float* __restrict__ sentJ,
    const float* __restrict__ gateE, const float* __restrict__ keyJ,
    const float* __restrict__ embed,
    const __nv_bfloat16* __restrict__ wimg, float* __restrict__ mem)
{
    extern __shared__ char sc[];
    unsigned sb = smem_u32(sc);
    float* sSent=(float*)(sc+OSE); float* sSJ=(float*)(sc+OSJ);
    float* sUb=(float*)(sc+OUB);   float* sKJ=(float*)(sc+OKJ);
    unsigned uSHI=sb+SHI, uSLO=sb+SLO, uOB=sb+OB;

    int tid=threadIdx.x, w=tid>>5, lane=tid&31, tig=lane&3;
    int r0=blockIdx.x*128;
    int rA=16*w+(lane>>2), rB=rA+8;
    int grA=r0+rA, grB=r0+rB;
    int b0=r0/20;
    int mA=grA%20, mB=grB%20, bbA=grA/20-b0, bbB=grB/20-b0;
    float alpha=pa[0];

    for (int i=tid;i<256;i+=256) sUb[i]=Ub_[i];
    for (int i=tid;i<5120;i+=256){int col=i/20,mm=i%20; sKJ[i]=keyJ[mm*256+col]+Jb_[col];}
    {   // init S = embed[m] hi/lo
        int row=tid>>1, c0=(tid&1)*128, mm=(r0+row)%20;
        for (int c=0;c<128;c+=2){
            uint32_t lo, hi=packsplit(embed[mm*256+c0+c], embed[mm*256+c0+c+1], lo);
            *(uint32_t*)(sc+SHI+row*528+(c0+c)*2)=hi;
            *(uint32_t*)(sc+SLO+row*528+(c0+c)*2)=lo;
        }
    }
    __syncthreads();

    unsigned aRow=(unsigned)(16*w+(lane&15))*528u;
    unsigned aK8 =(lane>=16)?16u:0u;
    unsigned bRow=(unsigned)((lane&7)+((lane>>4)<<3))*80u;
    unsigned bK8 =(lane&8)?16u:0u;

    int cc=0;
    cp_chunk(wimg, uOB,          0, tid);
    cp_chunk(wimg, uOB+20480u,   1, tid);

    float inv0=1.f, inv1=1.f;
    uint32_t A1h[64], A1l[64];

    for (int s=0; s<SEQ; s++){
        for (int i=tid;i<2048;i+=256){
            int bb=i>>8, n=i&255; float v1=0.f,v2=0.f;
            if (b0+bb<BSZ){ size_t o=((size_t)s*BSZ+b0+bb)*256+n; v1=mi[o]; v2=sentJ[o]; }
            sSent[i]=v1; sSJ[i]=v2;
        }
        __syncthreads();

        // gate: inv*(S.sent) + gateE
        float d0=0.f, d1=0.f;
#pragma unroll
        for (int i=0;i<8;i++){
            int off=tig*128+16*i;
            uint4 hA=*(const uint4*)(sc+SHI+rA*528+off), lA=*(const uint4*)(sc+SLO+rA*528+off);
            uint4 hB=*(const uint4*)(sc+SHI+rB*528+off), lB=*(const uint4*)(sc+SLO+rB*528+off);
            const float* sA_=sSent+bbA*256+tig*64+8*i;
            const float* sB_=sSent+bbB*256+tig*64+8*i;
            uint32_t ha[4]={hA.x,hA.y,hA.z,hA.w}, la[4]={lA.x,lA.y,lA.z,lA.w};
            uint32_t hb[4]={hB.x,hB.y,hB.z,hB.w}, lb[4]={lB.x,lB.y,lB.z,lB.w};
#pragma unroll
            for (int j=0;j<4;j++){
                float2 x=bf2u(ha[j]), y=bf2u(la[j]);
                d0 += (x.x+y.x)*sA_[2*j] + (x.y+y.y)*sA_[2*j+1];
                float2 u=bf2u(hb[j]), v=bf2u(lb[j]);
                d1 += (u.x+v.x)*sB_[2*j] + (u.y+v.y)*sB_[2*j+1];
            }
        }
        d0+=__shfl_xor_sync(0xffffffffu,d0,1); d0+=__shfl_xor_sync(0xffffffffu,d0,2);
        d1+=__shfl_xor_sync(0xffffffffu,d1,1); d1+=__shfl_xor_sync(0xffffffffu,d1,2);
        float g0=1.f/(1.f+expf(-(inv0*d0+gateE[(size_t)s*20480+grA])));
        float g1=1.f/(1.f+expf(-(inv1*d1+gateE[(size_t)s*20480+grB])));

        // ---- GEMM1: D = S @ U^T (two n-halves) ----
#pragma unroll
        for (int h=0;h<2;h++){
            float C[16][4];
#pragma unroll
            for (int i=0;i<16;i++){C[i][0]=0.f;C[i][1]=0.f;C[i][2]=0.f;C[i][3]=0.f;}
#pragma unroll 1
            for (int kc=0;kc<8;kc++){
                cp_wait<1>(); __syncthreads();
                unsigned bbuf = uOB + (unsigned)(cc&1)*20480u;
#pragma unroll
                for (int ks=0;ks<2;ks++){
                    uint32_t ah[4],al[4];
                    unsigned ka=(unsigned)((32*kc+16*ks)*2)+aK8;
                    ldsm4(ah, uSHI+aRow+ka); ldsm4(al, uSLO+aRow+ka);
#pragma unroll
                    for (int np=0;np<8;np++){
                        uint32_t bh[4],bl[4];
                        unsigned ba=bbuf+bRow+(unsigned)(np*1280)+(unsigned)(ks*32)+bK8;
                        ldsm4(bh, ba); ldsm4(bl, ba+10240u);
                        mma_(C[2*np],  ah,bh[0],bh[1]); mma_(C[2*np],  al,bh[0],bh[1]); mma_(C[2*np],  ah,bl[0],bl[1]);
                        mma_(C[2*np+1],ah,bh[2],bh[3]); mma_(C[2*np+1],al,bh[2],bh[3]); mma_(C[2*np+1],ah,bl[2],bl[3]);
                    }
                }
                __syncthreads();
                cp_chunk(wimg, uOB+(unsigned)(cc&1)*20480u, (cc+2)&31, tid);
                cc++;
            }
            // A1 = relu(inv*C + Ub) -> register fragments (hi/lo)
#pragma unroll
            for (int nt=0;nt<16;nt++){
                int col=128*h+8*nt+2*tig;
                float2 ub=*(const float2*)(sUb+col);
                float v0=fmaxf(inv0*C[nt][0]+ub.x,0.f), v1=fmaxf(inv0*C[nt][1]+ub.y,0.f);
                float v2=fmaxf(inv1*C[nt][2]+ub.x,0.f), v3=fmaxf(inv1*C[nt][3]+ub.y,0.f);
                int j4=4*(8*h+(nt>>1))+(nt&1)*2;
                A1h[j4]  =packsplit(v0,v1,A1l[j4]);
                A1h[j4+1]=packsplit(v2,v3,A1l[j4+1]);
            }
        }

        // ---- GEMM2: D = A1 @ J1^T + epilogue per half ----
        float ss0=0.f, ss1=0.f;
#pragma unroll
        for (int h=0;h<2;h++){
            float C[16][4];
#pragma unroll
            for (int i=0;i<16;i++){C[i][0]=0.f;C[i][1]=0.f;C[i][2]=0.f;C[i][3]=0.f;}
#pragma unroll
            for (int kc=0;kc<8;kc++){
                cp_wait<1>(); __syncthreads();
                unsigned bbuf = uOB + (unsigned)(cc&1)*20480u;
#pragma unroll
                for (int ks=0;ks<2;ks++){
                    int j=2*kc+ks;
                    const uint32_t* ah=&A1h[4*j]; const uint32_t* al=&A1l[4*j];
#pragma unroll
                    for (int np=0;np<8;np++){
                        uint32_t bh[4],bl[4];
                        unsigned ba=bbuf+bRow+(unsigned)(np*1280)+(unsigned)(ks*32)+bK8;
                        ldsm4(bh, ba); ldsm4(bl, ba+10240u);
                        mma_(C[2*np],  ah,bh[0],bh[1]); mma_(C[2*np],  al,bh[0],bh[1]); mma_(C[2*np],  ah,bl[0],bl[1]);
                        mma_(C[2*np+1],ah,bh[2],bh[3]); mma_(C[2*np+1],al,bh[2],bh[3]); mma_(C[2*np+1],ah,bl[2],bl[3]);
                    }
                }
                __syncthreads();
                cp_chunk(wimg, uOB+(unsigned)(cc&1)*20480u, (cc+2)&31, tid);
                cc++;
            }
            // epilogue half h: cand -> u -> S (raw, inv folded)
#pragma unroll
            for (int nt=0;nt<16;nt++){
                int col=128*h+8*nt+2*tig;
                float c0=C[nt][0]+sKJ[col*20+mA]+sSJ[bbA*256+col];
                float c1=C[nt][1]+sKJ[(col+1)*20+mA]+sSJ[bbA*256+col+1];
                float c2=C[nt][2]+sKJ[col*20+mB]+sSJ[bbB*256+col];
                float c3=C[nt][3]+sKJ[(col+1)*20+mB]+sSJ[bbB*256+col+1];
                c0=c0>0.f?c0:alpha*c0; c1=c1>0.f?c1:alpha*c1;
                c2=c2>0.f?c2:alpha*c2; c3=c3>0.f?c3:alpha*c3;
                unsigned oA=rA*528+col*2, oB=rB*528+col*2;
                float2 fh=bf2u(*(uint32_t*)(sc+SHI+oA)), fl=bf2u(*(uint32_t*)(sc+SLO+oA));
                float u0=inv0*(fh.x+fl.x)+g0*c0, u1=inv0*(fh.y+fl.y)+g0*c1;
                ss0+=u0*u0+u1*u1;
                uint32_t lo,hi=packsplit(u0,u1,lo);
                *(uint32_t*)(sc+SHI+oA)=hi; *(uint32_t*)(sc+SLO+oA)=lo;
                fh=bf2u(*(uint32_t*)(sc+SHI+oB)); fl=bf2u(*(uint32_t*)(sc+SLO+oB));
                float u2=inv1*(fh.x+fl.x)+g1*c2, u3=inv1*(fh.y+fl.y)+g1*c3;
                ss1+=u2*u2+u3*u3;
                hi=packsplit(u2,u3,lo);
                *(uint32_t*)(sc+SHI+oB)=hi; *(uint32_t*)(sc+SLO+oB)=lo;
            }
        }
        ss0+=__shfl_xor_sync(0xffffffffu,ss0,1); ss0+=__shfl_xor_sync(0xffffffffu,ss0,2);
        ss1+=__shfl_xor_sync(0xffffffffu,ss1,1); ss1+=__shfl_xor_sync(0xffffffffu,ss1,2);
        inv0=1.f/(sqrtf(ss0)+1e-12f);
        inv1=1.f/(sqrtf(ss1)+1e-12f);
        __syncthreads();
    }

    // final output: mem = inv * (Shi + Slo)
#pragma unroll
    for (int i=0;i<8;i++){
        int off=tig*128+16*i;
        uint4 hA=*(const uint4*)(sc+SHI+rA*528+off), lA=*(const uint4*)(sc+SLO+rA*528+off);
        uint4 hB=*(const uint4*)(sc+SHI+rB*528+off), lB=*(const uint4*)(sc+SLO+rB*528+off);
        uint32_t ha[4]={hA.x,hA.y,hA.z,hA.w}, la[4]={lA.x,lA.y,lA.z,lA.w};
        uint32_t hb[4]={hB.x,hB.y,hB.z,hB.w}, lb[4]={lB.x,lB.y,lB.z,lB.w};
#pragma unroll
        for (int j=0;j<4;j++){
            float2 x=bf2u(ha[j]), y=bf2u(la[j]);
            mem[(size_t)grA*256+tig*64+8*i+2*j]   = inv0*(x.x+y.x);
            mem[(size_t)grA*256+tig*64+8*i+2*j+1] = inv0*(x.y+y.y);
            float2 u=bf2u(hb[j]), v=bf2u(lb[j]);
            mem[(size_t)grB*256+tig*64+8*i+2*j]   = inv1*(u.x+v.x);
            mem[(size_t)grB*256+tig*64+8*i+2*j+1] = inv1*(u.y+v.y);
        }
    }
    cp_wait<0>();
}

// ---------------- precompute kernels (unchanged, known-good) ----------------
__global__ void __launch_bounds__(256) gemm256(
    const float* __restrict__ A, int lda, int rows, int K,
    const float* __restrict__ B, int ldb,
    const float* __restrict__ bias, float* __restrict__ C, int act)
{
    extern __shared__ float sm[];
    float* sA = sm; float* sBt = sm + BM*KC; float* sBias = sBt + KC*257;
    int tid = threadIdx.x, rt = tid>>5, ct = tid&31;
    long r0 = (long)blockIdx.x * BM;
    sBias[tid] = bias ? bias[tid] : 0.f;
    float acc[8][8];
#pragma unroll
    for (int i=0;i<8;i++)
#pragma unroll
        for (int j=0;j<8;j++) acc[i][j]=0.f;
    for (int k0=0;k0<K;k0+=KC){
#pragma unroll 4
        for (int t=tid;t<BM*KC;t+=256){
            int row=t>>6, kk=t&63; int k=k0+kk; long r=r0+row;
            sA[t] = (k<K && r<rows) ? A[r*(long)lda+k] : 0.f;
        }
#pragma unroll 8
        for (int t=tid;t<256*KC;t+=256){
            int n=t>>6, kk=t&63; int k=k0+kk;
            sBt[kk*257+n] = (k<K) ? B[(long)n*ldb+k] : 0.f;
        }
        __syncthreads();
#pragma unroll 8
        for (int kk=0;kk<KC;kk++){
            float a[8], bv[8];
#pragma unroll
            for (int i=0;i<8;i++) a[i]=sA[(rt*8+i)*KC+kk];
#pragma unroll
            for (int j=0;j<8;j++) bv[j]=sBt[kk*257+ct+j*32];
#pragma unroll
            for (int i=0;i<8;i++)
#pragma unroll
                for (int j=0;j<8;j++) acc[i][j]=fmaf(a[i],bv[j],acc[i][j]);
        }
        __syncthreads();
    }
#pragma unroll
    for (int i=0;i<8;i++){
        long row=r0+rt*8+i;
        if (row<rows)
#pragma unroll
            for (int j=0;j<8;j++){
                int col=ct+j*32; float v=acc[i][j]+sBias[col];
                if (act==1) v=fmaxf(v,0.f);
                C[row*256+col]=v;
            }
    }
}

__global__ void __launch_bounds__(256) gatee_kernel(
    const float* __restrict__ mi, const float* __restrict__ embed, float* __restrict__ out)
{
    extern __shared__ float sm[];
    float* sMi = sm; float* sE = sm + 64*256;
    int tid = threadIdx.x, ct = tid & 31;
    long r0 = (long)blockIdx.x * 64;
    {
        const float4* g4=(const float4*)(mi+r0*256); float4* s4=(float4*)sMi;
#pragma unroll 4
        for (int i=tid;i<64*64;i+=256) s4[i]=g4[i];
        const float4* e4=(const float4*)embed; float4* se4=(float4*)sE;
        for (int i=tid;i<20*64;i+=256) se4[i]=e4[i];
    }
    __syncthreads();
#pragma unroll
    for (int q=0;q<5;q++){
        int o=q*256+tid; int row=o/20, mm=o%20;
        float acc=0.f;
#pragma unroll 8
        for (int k=0;k<256;k++){
            int kr=(k+ct*8)&255;
            acc += sMi[row*256+kr]*sE[mm*256+kr];
        }
        out[r0*20+o]=acc;
    }
}

__global__ void __launch_bounds__(256) attn_kernel(
    const float* __restrict__ mem, const float* __restrict__ q, float* __restrict__ cat)
{
    __shared__ float sQ[256]; __shared__ float sM[MSLOT*256]; __shared__ float sE[MSLOT];
    int b = blockIdx.x, tid = threadIdx.x;
    sQ[tid] = q[(long)b*256+tid];
    for (int t=tid;t<MSLOT*256;t+=256) sM[t]=mem[(long)b*MSLOT*256+t];
    __syncthreads();
    int w=tid>>5, l=tid&31;
    for (int mm=w;mm<MSLOT;mm+=8){
        float p=0.f;
        for (int k=l;k<256;k+=32) p+=sM[mm*256+k]*sQ[k];
#pragma unroll
        for (int o=16;o>0;o>>=1) p+=__shfl_xor_sync(0xffffffffu,p,o);
        if (l==0) sE[mm]=p;
    }
    __syncthreads();
    float mx=-1e30f;
    for (int mm=0;mm<MSLOT;mm++) mx=fmaxf(mx,sE[mm]);
    float sum=0.f;
    for (int mm=0;mm<MSLOT;mm++) sum+=expf(sE[mm]-mx);
    float att=0.f;
    for (int mm=0;mm<MSLOT;mm++) att+=sM[mm*256+tid]*expf(sE[mm]-mx);
    att/=sum;
    cat[(long)b*512+tid]=sQ[tid];
    cat[(long)b*512+256+tid]=att;
}

extern "C" void kernel_launch(void* const* d_in, const int* in_sizes, int n_in,
                              void* d_out, int out_size)
{
    const float* memory_inputs=(const float*)d_in[0];
    const float* question=(const float*)d_in[1];
    const float* C_w=(const float*)d_in[2]; const float* C_b=(const float*)d_in[3];
    const float* Q_w=(const float*)d_in[4]; const float* Q_b=(const float*)d_in[5];
    const float* H_w=(const float*)d_in[6]; const float* H_b=(const float*)d_in[7];
    const float* U_w=(const float*)d_in[8]; const float* U_b=(const float*)d_in[9];
    const float* V_w=(const float*)d_in[10]; const float* V_b=(const float*)d_in[11];
    const float* W_w=(const float*)d_in[12]; const float* W_b=(const float*)d_in[13];
    const float* J_w=(const float*)d_in[14]; const float* J_b=(const float*)d_in[15];
    const float* prelu_a=(const float*)d_in[16];
    const float* embed=(const float*)d_in[17];
    float* out=(float*)d_out;

    size_t gemm_smem=(size_t)(BM*KC+KC*257+256)*sizeof(float);
    size_t gatee_smem=(size_t)(64*256+20*256)*sizeof(float);
    cudaFuncSetAttribute(gemm256, cudaFuncAttributeMaxDynamicSharedMemorySize,(int)gemm_smem);
    cudaFuncSetAttribute(gatee_kernel, cudaFuncAttributeMaxDynamicSharedMemorySize,(int)gatee_smem);
    cudaFuncSetAttribute(scan_mma, cudaFuncAttributeMaxDynamicSharedMemorySize,(int)STOT);

    float *mi,*tmp,*sentJ,*memb,*q,*a3,*keyJ,*cat,*gateE; __nv_bfloat16* wimg;
    cudaGetSymbolAddress((void**)&mi, g_mi);
    cudaGetSymbolAddress((void**)&tmp, g_tmp);
    cudaGetSymbolAddress((void**)&sentJ, g_sentJ);
    cudaGetSymbolAddress((void**)&memb, g_mem);
    cudaGetSymbolAddress((void**)&q, g_q);
    cudaGetSymbolAddress((void**)&a3, g_a3);
    cudaGetSymbolAddress((void**)&keyJ, g_keyJ);
    cudaGetSymbolAddress((void**)&cat, g_cat);
    cudaGetSymbolAddress((void**)&gateE, g_gateE);
    cudaGetSymbolAddress((void**)&wimg, g_wimg);

    wgt_build<<<32,256>>>(U_w, J_w, wimg);
    gemm256<<<SB/BM,256,gemm_smem>>>(memory_inputs,DIN,SB,DIN,C_w,DIN,C_b,mi,1);
    gemm256<<<BSZ/BM,256,gemm_smem>>>(question,QDIM,BSZ,QDIM,Q_w,QDIM,Q_b,q,1);
    gatee_kernel<<<SB/64,256,gatee_smem>>>(mi,embed,gateE);
    gemm256<<<SB/BM,256,gemm_smem>>>(mi,HID,SB,HID,V_w,HID,V_b,tmp,1);
    gemm256<<<SB/BM,256,gemm_smem>>>(tmp,HID,SB,HID,J_w+256,768,(const float*)0,sentJ,0);
    gemm256<<<1,256,gemm_smem>>>(embed,HID,MSLOT,HID,W_w,HID,W_b,a3,1);
    gemm256<<<1,256,gemm_smem>>>(a3,HID,MSLOT,HID,J_w+512,768,(const float*)0,keyJ,0);

    scan_mma<<<160,256,STOT>>>(U_b,J_b,prelu_a,mi,sentJ,gateE,keyJ,embed,wimg,memb);

    attn_kernel<<<BSZ,256>>>(memb,q,cat);
    gemm256<<<BSZ/BM,256,gemm_smem>>>(cat,2*HID,BSZ,2*HID,H_w,2*HID,H_b,out,1);
}

// round 17
// speedup vs baseline: 1.5982x; 1.1462x over previous
#include <cuda_runtime.h>
#include <cuda_bf16.h>
#include <cstdint>

#define SEQ 128
#define BSZ 1024
#define DIN 37
#define QDIM 11
#define HID 256
#define MSLOT 20
#define ROWS (BSZ*MSLOT)
#define SB (SEQ*BSZ)
#define BM 64
#define KC 64

// scan smem byte offsets (64-row tile)
#define SHI 0u
#define SLO 33792u
#define OB  67584u
#define OUB 108544u
#define STOT 109568u

__device__ float g_mi[(size_t)SB*HID];
__device__ float g_tmp[(size_t)SB*HID];
__device__ float g_sentJ[(size_t)SB*HID];
__device__ float g_mem[(size_t)ROWS*HID];
__device__ float g_q[(size_t)BSZ*HID];
__device__ float g_a3[(size_t)MSLOT*HID];
__device__ float g_keyJ[(size_t)MSLOT*HID];
__device__ float g_kjb[(size_t)MSLOT*HID];
__device__ float g_cat[(size_t)BSZ*2*HID];
__device__ float g_gateE[(size_t)SB*MSLOT];
__device__ __nv_bfloat16 g_wimg[32*8192];

__device__ __forceinline__ unsigned smem_u32(const void* p){
    unsigned r; asm("{ .reg .u64 t; cvta.to.shared.u64 t, %1; cvt.u32.u64 %0, t; }":"=r"(r):"l"(p)); return r;
}
__device__ __forceinline__ void cp_async16(unsigned s,const void* g){
    asm volatile("cp.async.cg.shared.global [%0], [%1], 16;"::"r"(s),"l"(g));
}
__device__ __forceinline__ void cp_commit(){ asm volatile("cp.async.commit_group;"); }
template<int N> __device__ __forceinline__ void cp_wait(){ asm volatile("cp.async.wait_group %0;"::"n"(N)); }

__device__ __forceinline__ void ldsm4(uint32_t* r, unsigned a){
    asm volatile("ldmatrix.sync.aligned.m8n8.x4.shared.b16 {%0,%1,%2,%3}, [%4];"
        :"=r"(r[0]),"=r"(r[1]),"=r"(r[2]),"=r"(r[3]):"r"(a));
}
__device__ __forceinline__ void mma_(float* c, const uint32_t* a, uint32_t b0, uint32_t b1){
    asm volatile("mma.sync.aligned.m16n8k16.row.col.f32.bf16.bf16.f32 "
        "{%0,%1,%2,%3},{%4,%5,%6,%7},{%8,%9},{%0,%1,%2,%3};"
        :"+f"(c[0]),"+f"(c[1]),"+f"(c[2]),"+f"(c[3])
        :"r"(a[0]),"r"(a[1]),"r"(a[2]),"r"(a[3]),"r"(b0),"r"(b1));
}
__device__ __forceinline__ float2 bf2u(uint32_t w){
    __nv_bfloat162 t=*(__nv_bfloat162*)&w; return make_float2(__bfloat162float(t.x),__bfloat162float(t.y));
}
__device__ __forceinline__ uint32_t packsplit(float a,float b,uint32_t& lo){
    __nv_bfloat16 ha=__float2bfloat16(a), hb=__float2bfloat16(b);
    __nv_bfloat162 L; L.x=__float2bfloat16(a-__bfloat162float(ha)); L.y=__float2bfloat16(b-__bfloat162float(hb));
    lo=*(uint32_t*)&L; __nv_bfloat162 H; H.x=ha; H.y=hb; return *(uint32_t*)&H;
}

// weight chunk images: c = g*16 + h*8 + kc ; content [p][n128][k32] bf16
__global__ void wgt_build(const float* __restrict__ U_w, const float* __restrict__ J_w,
                          __nv_bfloat16* __restrict__ out)
{
    int c = blockIdx.x;
    int g = (c>>4)&1, h = (c>>3)&1, kc = c&7;
    const float* W = g ? J_w : U_w;
    int ld = g ? 768 : 256;
    __nv_bfloat16* dst = out + (size_t)c*8192;
    for (int e = threadIdx.x; e < 8192; e += 256) {
        int p = e>>12, n = (e>>5)&127, k = e&31;
        float w = W[(size_t)(h*128+n)*ld + kc*32 + k];
        __nv_bfloat16 hi = __float2bfloat16(w);
        dst[e] = p ? __float2bfloat16(w - __bfloat162float(hi)) : hi;
    }
}

__global__ void kjb_build(const float* __restrict__ keyJ, const float* __restrict__ Jb,
                          float* __restrict__ kjb)
{
    int i = blockIdx.x*256 + threadIdx.x;
    if (i < MSLOT*256) kjb[i] = keyJ[i] + Jb[i & 255];
}

// 128-thread chunk copy into padded [p][n128][k32] smem (80B row stride)
__device__ __forceinline__ void cp_chunk(const __nv_bfloat16* wimg, unsigned dst, int img, int tid){
    const char* src = (const char*)wimg + (size_t)img*16384;
#pragma unroll
    for (int it=0; it<8; it++){
        int ci = tid + it*128;
        int p = ci>>9, n = (ci>>2)&127, u = ci&3;
        cp_async16(dst + (unsigned)(p*10240 + n*80 + u*16), src + p*8192 + n*64 + u*16);
    }
    cp_commit();
}

__global__ void __launch_bounds__(128,2) scan_mma(
    const float* __restrict__ Ub_, const float* __restrict__ pa,
    const float* __restrict__ mi, const float* __restrict__ sentJ,
    const float* __restrict__ gateE, const float* __restrict__ kjb,
    const float* __restrict__ embed,
    const __nv_bfloat16* __restrict__ wimg, float* __restrict__ mem)
{
    extern __shared__ char sc[];
    unsigned sb = smem_u32(sc);
    float* sUb=(float*)(sc+OUB);
    unsigned uSHI=sb+SHI, uSLO=sb+SLO, uOB=sb+OB;

    int tid=threadIdx.x, w=tid>>5, lane=tid&31, tig=lane&3;
    int r0=blockIdx.x*64;
    int rA=16*w+(lane>>2), rB=rA+8;
    int grA=r0+rA, grB=r0+rB;
    int mA=grA%20, mB=grB%20;
    int gbA=grA/20, gbB=grB/20;
    float alpha=pa[0];

    for (int i=tid;i<256;i+=128) sUb[i]=Ub_[i];
    {   // init S = embed[m] hi/lo  (row = tid>>1, half = tid&1)
        int row=tid>>1, c0=(tid&1)*128, mm=(r0+row)%20;
        for (int c=0;c<128;c+=2){
            uint32_t lo, hi=packsplit(embed[mm*256+c0+c], embed[mm*256+c0+c+1], lo);
            *(uint32_t*)(sc+SHI+row*528+(c0+c)*2)=hi;
            *(uint32_t*)(sc+SLO+row*528+(c0+c)*2)=lo;
        }
    }
    __syncthreads();

    unsigned aRow=(unsigned)(16*w+(lane&15))*528u;
    unsigned aK8 =(lane>=16)?16u:0u;
    unsigned bRow=(unsigned)((lane&7)+((lane>>4)<<3))*80u;
    unsigned bK8 =(lane&8)?16u:0u;

    int cc=0;
    cp_chunk(wimg, uOB,        0, tid);
    cp_chunk(wimg, uOB+20480u, 1, tid);

    float inv0=1.f, inv1=1.f;
    uint32_t A1h[64], A1l[64];

    for (int s=0; s<SEQ; s++){
        // gate: inv*(S.sent) + gateE   (sent read from global; L1 serves reuse)
        const float* seA = mi + ((size_t)s*BSZ + gbA)*256;
        const float* seB = mi + ((size_t)s*BSZ + gbB)*256;
        float d0=0.f, d1=0.f;
#pragma unroll
        for (int i=0;i<8;i++){
            int off=tig*128+16*i;
            uint4 hA=*(const uint4*)(sc+SHI+rA*528+off), lA=*(const uint4*)(sc+SLO+rA*528+off);
            uint4 hB=*(const uint4*)(sc+SHI+rB*528+off), lB=*(const uint4*)(sc+SLO+rB*528+off);
            uint32_t ha[4]={hA.x,hA.y,hA.z,hA.w}, la[4]={lA.x,lA.y,lA.z,lA.w};
            uint32_t hb[4]={hB.x,hB.y,hB.z,hB.w}, lb[4]={lB.x,lB.y,lB.z,lB.w};
#pragma unroll
            for (int j=0;j<4;j++){
                float2 sa=*(const float2*)(seA + tig*64+8*i+2*j);
                float2 sbv=*(const float2*)(seB + tig*64+8*i+2*j);
                float2 x=bf2u(ha[j]), y=bf2u(la[j]);
                d0 += (x.x+y.x)*sa.x + (x.y+y.y)*sa.y;
                float2 u=bf2u(hb[j]), v=bf2u(lb[j]);
                d1 += (u.x+v.x)*sbv.x + (u.y+v.y)*sbv.y;
            }
        }
        d0+=__shfl_xor_sync(0xffffffffu,d0,1); d0+=__shfl_xor_sync(0xffffffffu,d0,2);
        d1+=__shfl_xor_sync(0xffffffffu,d1,1); d1+=__shfl_xor_sync(0xffffffffu,d1,2);
        float g0=1.f/(1.f+expf(-(inv0*d0+gateE[(size_t)s*20480+grA])));
        float g1=1.f/(1.f+expf(-(inv1*d1+gateE[(size_t)s*20480+grB])));

        // ---- GEMM1: D = S @ U^T (two n-halves) ----
#pragma unroll
        for (int h=0;h<2;h++){
            float C[16][4];
#pragma unroll
            for (int i=0;i<16;i++){C[i][0]=0.f;C[i][1]=0.f;C[i][2]=0.f;C[i][3]=0.f;}
#pragma unroll 1
            for (int kc=0;kc<8;kc++){
                cp_wait<1>(); __syncthreads();
                unsigned bbuf = uOB + (unsigned)(cc&1)*20480u;
#pragma unroll
                for (int ks=0;ks<2;ks++){
                    uint32_t ah[4],al[4];
                    unsigned ka=(unsigned)((32*kc+16*ks)*2)+aK8;
                    ldsm4(ah, uSHI+aRow+ka); ldsm4(al, uSLO+aRow+ka);
#pragma unroll
                    for (int np=0;np<8;np++){
                        uint32_t bh[4],bl[4];
                        unsigned ba=bbuf+bRow+(unsigned)(np*1280)+(unsigned)(ks*32)+bK8;
                        ldsm4(bh, ba); ldsm4(bl, ba+10240u);
                        mma_(C[2*np],  ah,bh[0],bh[1]); mma_(C[2*np],  al,bh[0],bh[1]); mma_(C[2*np],  ah,bl[0],bl[1]);
                        mma_(C[2*np+1],ah,bh[2],bh[3]); mma_(C[2*np+1],al,bh[2],bh[3]); mma_(C[2*np+1],ah,bl[2],bl[3]);
                    }
                }
                __syncthreads();
                cp_chunk(wimg, uOB+(unsigned)(cc&1)*20480u, (cc+2)&31, tid);
                cc++;
            }
            // A1 = relu(inv*C + Ub) -> register fragments (hi/lo)
#pragma unroll
            for (int nt=0;nt<16;nt++){
                int col=128*h+8*nt+2*tig;
                float2 ub=*(const float2*)(sUb+col);
                float v0=fmaxf(inv0*C[nt][0]+ub.x,0.f), v1=fmaxf(inv0*C[nt][1]+ub.y,0.f);
                float v2=fmaxf(inv1*C[nt][2]+ub.x,0.f), v3=fmaxf(inv1*C[nt][3]+ub.y,0.f);
                int j4=4*(8*h+(nt>>1))+(nt&1)*2;
                A1h[j4]  =packsplit(v0,v1,A1l[j4]);
                A1h[j4+1]=packsplit(v2,v3,A1l[j4+1]);
            }
        }

        // ---- GEMM2: D = A1 @ J1^T + epilogue per half ----
        const float* sjA = sentJ + ((size_t)s*BSZ + gbA)*256;
        const float* sjB = sentJ + ((size_t)s*BSZ + gbB)*256;
        const float* kjA = kjb + mA*256;
        const float* kjB = kjb + mB*256;
        float ss0=0.f, ss1=0.f;
#pragma unroll
        for (int h=0;h<2;h++){
            float C[16][4];
#pragma unroll
            for (int i=0;i<16;i++){C[i][0]=0.f;C[i][1]=0.f;C[i][2]=0.f;C[i][3]=0.f;}
#pragma unroll
            for (int kc=0;kc<8;kc++){
                cp_wait<1>(); __syncthreads();
                unsigned bbuf = uOB + (unsigned)(cc&1)*20480u;
#pragma unroll
                for (int ks=0;ks<2;ks++){
                    int j=2*kc+ks;
                    const uint32_t* ah=&A1h[4*j]; const uint32_t* al=&A1l[4*j];
#pragma unroll
                    for (int np=0;np<8;np++){
                        uint32_t bh[4],bl[4];
                        unsigned ba=bbuf+bRow+(unsigned)(np*1280)+(unsigned)(ks*32)+bK8;
                        ldsm4(bh, ba); ldsm4(bl, ba+10240u);
                        mma_(C[2*np],  ah,bh[0],bh[1]); mma_(C[2*np],  al,bh[0],bh[1]); mma_(C[2*np],  ah,bl[0],bl[1]);
                        mma_(C[2*np+1],ah,bh[2],bh[3]); mma_(C[2*np+1],al,bh[2],bh[3]); mma_(C[2*np+1],ah,bl[2],bl[3]);
                    }
                }
                __syncthreads();
                cp_chunk(wimg, uOB+(unsigned)(cc&1)*20480u, (cc+2)&31, tid);
                cc++;
            }
            // epilogue half h: cand -> u -> S (raw, inv folded)
#pragma unroll
            for (int nt=0;nt<16;nt++){
                int col=128*h+8*nt+2*tig;
                float2 kA=*(const float2*)(kjA+col), sA2=*(const float2*)(sjA+col);
                float2 kB=*(const float2*)(kjB+col), sB2=*(const float2*)(sjB+col);
                float c0=C[nt][0]+kA.x+sA2.x;
                float c1=C[nt][1]+kA.y+sA2.y;
                float c2=C[nt][2]+kB.x+sB2.x;
                float c3=C[nt][3]+kB.y+sB2.y;
                c0=c0>0.f?c0:alpha*c0; c1=c1>0.f?c1:alpha*c1;
                c2=c2>0.f?c2:alpha*c2; c3=c3>0.f?c3:alpha*c3;
                unsigned oA=rA*528+col*2, oB=rB*528+col*2;
                float2 fh=bf2u(*(uint32_t*)(sc+SHI+oA)), fl=bf2u(*(uint32_t*)(sc+SLO+oA));
                float u0=inv0*(fh.x+fl.x)+g0*c0, u1=inv0*(fh.y+fl.y)+g0*c1;
                ss0+=u0*u0+u1*u1;
                uint32_t lo,hi=packsplit(u0,u1,lo);
                *(uint32_t*)(sc+SHI+oA)=hi; *(uint32_t*)(sc+SLO+oA)=lo;
                fh=bf2u(*(uint32_t*)(sc+SHI+oB)); fl=bf2u(*(uint32_t*)(sc+SLO+oB));
                float u2=inv1*(fh.x+fl.x)+g1*c2, u3=inv1*(fh.y+fl.y)+g1*c3;
                ss1+=u2*u2+u3*u3;
                hi=packsplit(u2,u3,lo);
                *(uint32_t*)(sc+SHI+oB)=hi; *(uint32_t*)(sc+SLO+oB)=lo;
            }
        }
        ss0+=__shfl_xor_sync(0xffffffffu,ss0,1); ss0+=__shfl_xor_sync(0xffffffffu,ss0,2);
        ss1+=__shfl_xor_sync(0xffffffffu,ss1,1); ss1+=__shfl_xor_sync(0xffffffffu,ss1,2);
        inv0=1.f/(sqrtf(ss0)+1e-12f);
        inv1=1.f/(sqrtf(ss1)+1e-12f);
        __syncwarp();   // state is warp-private; warp-level fence suffices
    }

    // final output: mem = inv * (Shi + Slo)
#pragma unroll
    for (int i=0;i<8;i++){
        int off=tig*128+16*i;
        uint4 hA=*(const uint4*)(sc+SHI+rA*528+off), lA=*(const uint4*)(sc+SLO+rA*528+off);
        uint4 hB=*(const uint4*)(sc+SHI+rB*528+off), lB=*(const uint4*)(sc+SLO+rB*528+off);
        uint32_t ha[4]={hA.x,hA.y,hA.z,hA.w}, la[4]={lA.x,lA.y,lA.z,lA.w};
        uint32_t hb[4]={hB.x,hB.y,hB.z,hB.w}, lb[4]={lB.x,lB.y,lB.z,lB.w};
#pragma unroll
        for (int j=0;j<4;j++){
            float2 x=bf2u(ha[j]), y=bf2u(la[j]);
            mem[(size_t)grA*256+tig*64+8*i+2*j]   = inv0*(x.x+y.x);
            mem[(size_t)grA*256+tig*64+8*i+2*j+1] = inv0*(x.y+y.y);
            float2 u=bf2u(hb[j]), v=bf2u(lb[j]);
            mem[(size_t)grB*256+tig*64+8*i+2*j]   = inv1*(u.x+v.x);
            mem[(size_t)grB*256+tig*64+8*i+2*j+1] = inv1*(u.y+v.y);
        }
    }
    cp_wait<0>();
}

// ---------------- precompute kernels (unchanged, known-good) ----------------
__global__ void __launch_bounds__(256) gemm256(
    const float* __restrict__ A, int lda, int rows, int K,
    const float* __restrict__ B, int ldb,
    const float* __restrict__ bias, float* __restrict__ C, int act)
{
    extern __shared__ float sm[];
    float* sA = sm; float* sBt = sm + BM*KC; float* sBias = sBt + KC*257;
    int tid = threadIdx.x, rt = tid>>5, ct = tid&31;
    long r0 = (long)blockIdx.x * BM;
    sBias[tid] = bias ? bias[tid] : 0.f;
    float acc[8][8];
#pragma unroll
    for (int i=0;i<8;i++)
#pragma unroll
        for (int j=0;j<8;j++) acc[i][j]=0.f;
    for (int k0=0;k0<K;k0+=KC){
#pragma unroll 4
        for (int t=tid;t<BM*KC;t+=256){
            int row=t>>6, kk=t&63; int k=k0+kk; long r=r0+row;
            sA[t] = (k<K && r<rows) ? A[r*(long)lda+k] : 0.f;
        }
#pragma unroll 8
        for (int t=tid;t<256*KC;t+=256){
            int n=t>>6, kk=t&63; int k=k0+kk;
            sBt[kk*257+n] = (k<K) ? B[(long)n*ldb+k] : 0.f;
        }
        __syncthreads();
#pragma unroll 8
        for (int kk=0;kk<KC;kk++){
            float a[8], bv[8];
#pragma unroll
            for (int i=0;i<8;i++) a[i]=sA[(rt*8+i)*KC+kk];
#pragma unroll
            for (int j=0;j<8;j++) bv[j]=sBt[kk*257+ct+j*32];
#pragma unroll
            for (int i=0;i<8;i++)
#pragma unroll
                for (int j=0;j<8;j++) acc[i][j]=fmaf(a[i],bv[j],acc[i][j]);
        }
        __syncthreads();
    }
#pragma unroll
    for (int i=0;i<8;i++){
        long row=r0+rt*8+i;
        if (row<rows)
#pragma unroll
            for (int j=0;j<8;j++){
                int col=ct+j*32; float v=acc[i][j]+sBias[col];
                if (act==1) v=fmaxf(v,0.f);
                C[row*256+col]=v;
            }
    }
}

__global__ void __launch_bounds__(256) gatee_kernel(
    const float* __restrict__ mi, const float* __restrict__ embed, float* __restrict__ out)
{
    extern __shared__ float sm[];
    float* sMi = sm; float* sE = sm + 64*256;
    int tid = threadIdx.x, ct = tid & 31;
    long r0 = (long)blockIdx.x * 64;
    {
        const float4* g4=(const float4*)(mi+r0*256); float4* s4=(float4*)sMi;
#pragma unroll 4
        for (int i=tid;i<64*64;i+=256) s4[i]=g4[i];
        const float4* e4=(const float4*)embed; float4* se4=(float4*)sE;
        for (int i=tid;i<20*64;i+=256) se4[i]=e4[i];
    }
    __syncthreads();
#pragma unroll
    for (int q=0;q<5;q++){
        int o=q*256+tid; int row=o/20, mm=o%20;
        float acc=0.f;
#pragma unroll 8
        for (int k=0;k<256;k++){
            int kr=(k+ct*8)&255;
            acc += sMi[row*256+kr]*sE[mm*256+kr];
        }
        out[r0*20+o]=acc;
    }
}

__global__ void __launch_bounds__(256) attn_kernel(
    const float* __restrict__ mem, const float* __restrict__ q, float* __restrict__ cat)
{
    __shared__ float sQ[256]; __shared__ float sM[MSLOT*256]; __shared__ float sE[MSLOT];
    int b = blockIdx.x, tid = threadIdx.x;
    sQ[tid] = q[(long)b*256+tid];
    for (int t=tid;t<MSLOT*256;t+=256) sM[t]=mem[(long)b*MSLOT*256+t];
    __syncthreads();
    int w=tid>>5, l=tid&31;
    for (int mm=w;mm<MSLOT;mm+=8){
        float p=0.f;
        for (int k=l;k<256;k+=32) p+=sM[mm*256+k]*sQ[k];
#pragma unroll
        for (int o=16;o>0;o>>=1) p+=__shfl_xor_sync(0xffffffffu,p,o);
        if (l==0) sE[mm]=p;
    }
    __syncthreads();
    float mx=-1e30f;
    for (int mm=0;mm<MSLOT;mm++) mx=fmaxf(mx,sE[mm]);
    float sum=0.f;
    for (int mm=0;mm<MSLOT;mm++) sum+=expf(sE[mm]-mx);
    float att=0.f;
    for (int mm=0;mm<MSLOT;mm++) att+=sM[mm*256+tid]*expf(sE[mm]-mx);
    att/=sum;
    cat[(long)b*512+tid]=sQ[tid];
    cat[(long)b*512+256+tid]=att;
}

extern "C" void kernel_launch(void* const* d_in, const int* in_sizes, int n_in,
                              void* d_out, int out_size)
{
    const float* memory_inputs=(const float*)d_in[0];
    const float* question=(const float*)d_in[1];
    const float* C_w=(const float*)d_in[2]; const float* C_b=(const float*)d_in[3];
    const float* Q_w=(const float*)d_in[4]; const float* Q_b=(const float*)d_in[5];
    const float* H_w=(const float*)d_in[6]; const float* H_b=(const float*)d_in[7];
    const float* U_w=(const float*)d_in[8]; const float* U_b=(const float*)d_in[9];
    const float* V_w=(const float*)d_in[10]; const float* V_b=(const float*)d_in[11];
    const float* W_w=(const float*)d_in[12]; const float* W_b=(const float*)d_in[13];
    const float* J_w=(const float*)d_in[14]; const float* J_b=(const float*)d_in[15];
    const float* prelu_a=(const float*)d_in[16];
    const float* embed=(const float*)d_in[17];
    float* out=(float*)d_out;

    size_t gemm_smem=(size_t)(BM*KC+KC*257+256)*sizeof(float);
    size_t gatee_smem=(size_t)(64*256+20*256)*sizeof(float);
    cudaFuncSetAttribute(gemm256, cudaFuncAttributeMaxDynamicSharedMemorySize,(int)gemm_smem);
    cudaFuncSetAttribute(gatee_kernel, cudaFuncAttributeMaxDynamicSharedMemorySize,(int)gatee_smem);
    cudaFuncSetAttribute(scan_mma, cudaFuncAttributeMaxDynamicSharedMemorySize,(int)STOT);

    float *mi,*tmp,*sentJ,*memb,*q,*a3,*keyJ,*kjb,*cat,*gateE; __nv_bfloat16* wimg;
    cudaGetSymbolAddress((void**)&mi, g_mi);
    cudaGetSymbolAddress((void**)&tmp, g_tmp);
    cudaGetSymbolAddress((void**)&sentJ, g_sentJ);
    cudaGetSymbolAddress((void**)&memb, g_mem);
    cudaGetSymbolAddress((void**)&q, g_q);
    cudaGetSymbolAddress((void**)&a3, g_a3);
    cudaGetSymbolAddress((void**)&keyJ, g_keyJ);
    cudaGetSymbolAddress((void**)&kjb, g_kjb);
    cudaGetSymbolAddress((void**)&cat, g_cat);
    cudaGetSymbolAddress((void**)&gateE, g_gateE);
    cudaGetSymbolAddress((void**)&wimg, g_wimg);

    wgt_build<<<32,256>>>(U_w, J_w, wimg);
    gemm256<<<SB/BM,256,gemm_smem>>>(memory_inputs,DIN,SB,DIN,C_w,DIN,C_b,mi,1);
    gemm256<<<BSZ/BM,256,gemm_smem>>>(question,QDIM,BSZ,QDIM,Q_w,QDIM,Q_b,q,1);
    gatee_kernel<<<SB/64,256,gatee_smem>>>(mi,embed,gateE);
    gemm256<<<SB/BM,256,gemm_smem>>>(mi,HID,SB,HID,V_w,HID,V_b,tmp,1);
    gemm256<<<SB/BM,256,gemm_smem>>>(tmp,HID,SB,HID,J_w+256,768,(const float*)0,sentJ,0);
    gemm256<<<1,256,gemm_smem>>>(embed,HID,MSLOT,HID,W_w,HID,W_b,a3,1);
    gemm256<<<1,256,gemm_smem>>>(a3,HID,MSLOT,HID,J_w+512,768,(const float*)0,keyJ,0);
    kjb_build<<<20,256>>>(keyJ, J_b, kjb);

    scan_mma<<<ROWS/64,128,STOT>>>(U_b,prelu_a,mi,sentJ,gateE,kjb,embed,wimg,memb);

    attn_kernel<<<BSZ,256>>>(memb,q,cat);
    gemm256<<<BSZ/BM,256,gemm_smem>>>(cat,2*HID,BSZ,2*HID,H_w,2*HID,H_b,out,1);
}